// round 7
// baseline (speedup 1.0000x reference)
#include <cuda_runtime.h>
#include <math.h>

#define NNODES 50000
#define NEDGES 1600000

// ---------------- scratch (static device globals; no allocation) ----------------
__device__ float g_bufA[(size_t)NNODES * 2000];   // 400 MB
__device__ float g_bufB[(size_t)NNODES * 2000];   // 400 MB
__device__ float g_bufS0[NNODES * 10];
__device__ float g_bufS1[NNODES * 10];
__device__ int   g_rowptr[NNODES + 1];
__device__ int   g_cursor[NNODES + 1];
__device__ int   g_cols[NEDGES];
__device__ float g_vals[NEDGES];

// packed fp32x2 FMA (FFMA2) — ptxas never emits this from C++; 2x fp32 rate
__device__ __forceinline__ void ffma2(float2& d, const float2& a, const float2& b) {
    asm("fma.rn.f32x2 %0, %1, %2, %0;"
        : "+l"(*reinterpret_cast<unsigned long long*>(&d))
        : "l"(*reinterpret_cast<const unsigned long long*>(const_cast<float2*>(&a))),
          "l"(*reinterpret_cast<const unsigned long long*>(const_cast<float2*>(&b))));
}

// ---------------- CSR build (rebuilt every launch; deterministic inputs) --------
__global__ void k_zero_counts() {
    for (int i = blockIdx.x * blockDim.x + threadIdx.x; i <= NNODES;
         i += gridDim.x * blockDim.x)
        g_cursor[i] = 0;
}

__global__ void k_hist(const int* __restrict__ row) {
    for (int e = blockIdx.x * blockDim.x + threadIdx.x; e < NEDGES;
         e += gridDim.x * blockDim.x)
        atomicAdd(&g_cursor[row[e]], 1);
}

__global__ void k_scan() {  // single block, 1024 threads
    __shared__ int s[1024];
    const int CH = (NNODES + 1023) / 1024;  // 49
    int t = threadIdx.x;
    int beg = t * CH;
    int end = min(NNODES, beg + CH);
    int mysum = 0;
    for (int i = beg; i < end; i++) mysum += g_cursor[i];
    s[t] = mysum;
    __syncthreads();
    for (int off = 1; off < 1024; off <<= 1) {
        int v = (t >= off) ? s[t - off] : 0;
        __syncthreads();
        s[t] += v;
        __syncthreads();
    }
    int run = s[t] - mysum;  // exclusive prefix
    for (int i = beg; i < end; i++) {
        g_rowptr[i] = run;
        run += g_cursor[i];
    }
    if (t == 1023) g_rowptr[NNODES] = s[1023];
}

__global__ void k_reset_cursor() {
    for (int i = blockIdx.x * blockDim.x + threadIdx.x; i <= NNODES;
         i += gridDim.x * blockDim.x)
        g_cursor[i] = g_rowptr[i];
}

__global__ void k_scatter(const int* __restrict__ row, const int* __restrict__ col,
                          const float* __restrict__ vals) {
    for (int e = blockIdx.x * blockDim.x + threadIdx.x; e < NEDGES;
         e += gridDim.x * blockDim.x) {
        int p = atomicAdd(&g_cursor[row[e]], 1);
        g_cols[p] = col[e];
        g_vals[p] = vals[e];
    }
}

// ---------------- fp32 SGEMM, double-buffered smem + reg prefetch ----------------
// C[M,N] = op(A)[M,K] @ B[K,N];  op(A) = mixA ? 0.5*(A+Amix) : A.  Optional relu.
__global__ void __launch_bounds__(256, 2)
k_sgemm(const float* __restrict__ A, const float* __restrict__ Amix,
        const float* __restrict__ B, float* __restrict__ C,
        int M, int N, int K, int mixA, int reluOut) {
    const int BM = 128, BN = 128, BK = 16;
    __shared__ float As[2][BK][BM];   // 16 KB
    __shared__ float Bs[2][BK][BN];   // 16 KB
    int tid = threadIdx.x;
    int tx = tid & 15, ty = tid >> 4;
    int rowBase = blockIdx.y * BM, colBase = blockIdx.x * BN;

    // A loader: row aRow, k offsets aK0 and aK0+8 (float4 each)
    int aRow = tid >> 1;
    int aK0 = (tid & 1) * 4;
    int gr = rowBase + aRow;
    // B loader: k rows bK0 and bK0+8, col bCol (float4 each)
    int bK0 = tid >> 5;
    int bCol = (tid & 31) * 4;
    int gc = colBase + bCol;

    float2 acc2[8][4];
#pragma unroll
    for (int i = 0; i < 8; i++)
#pragma unroll
        for (int j = 0; j < 4; j++) acc2[i][j] = make_float2(0.f, 0.f);

    float4 pa0, pa1, pb0, pb1;

    // ---- load helpers (inlined manually) ----
#define LOAD_A(dst, k0, kofs)                                                   \
    {                                                                           \
        int gk = (k0) + aK0 + (kofs);                                           \
        dst = make_float4(0.f, 0.f, 0.f, 0.f);                                  \
        if (gr < M && gk < K) {                                                 \
            dst = *(const float4*)(A + (size_t)gr * K + gk);                    \
            if (mixA) {                                                         \
                float4 w = *(const float4*)(Amix + (size_t)gr * K + gk);        \
                dst.x = 0.5f * (dst.x + w.x);                                   \
                dst.y = 0.5f * (dst.y + w.y);                                   \
                dst.z = 0.5f * (dst.z + w.z);                                   \
                dst.w = 0.5f * (dst.w + w.w);                                   \
            }                                                                   \
        }                                                                       \
    }
#define LOAD_B(dst, k0, kofs)                                                   \
    {                                                                           \
        int gk = (k0) + bK0 + (kofs);                                           \
        dst = make_float4(0.f, 0.f, 0.f, 0.f);                                  \
        if (gk < K) {                                                           \
            if (gc + 3 < N) {                                                   \
                dst = *(const float4*)(B + (size_t)gk * N + gc);                \
            } else {                                                            \
                if (gc + 0 < N) dst.x = B[(size_t)gk * N + gc + 0];             \
                if (gc + 1 < N) dst.y = B[(size_t)gk * N + gc + 1];             \
                if (gc + 2 < N) dst.z = B[(size_t)gk * N + gc + 2];             \
            }                                                                   \
        }                                                                       \
    }
#define STS_TILE(buf)                                                           \
    {                                                                           \
        As[buf][aK0 + 0][aRow] = pa0.x;                                         \
        As[buf][aK0 + 1][aRow] = pa0.y;                                         \
        As[buf][aK0 + 2][aRow] = pa0.z;                                         \
        As[buf][aK0 + 3][aRow] = pa0.w;                                         \
        As[buf][aK0 + 8][aRow] = pa1.x;                                         \
        As[buf][aK0 + 9][aRow] = pa1.y;                                         \
        As[buf][aK0 + 10][aRow] = pa1.z;                                        \
        As[buf][aK0 + 11][aRow] = pa1.w;                                        \
        *(float4*)&Bs[buf][bK0][bCol] = pb0;                                    \
        *(float4*)&Bs[buf][bK0 + 8][bCol] = pb1;                                \
    }

    int numT = (K + BK - 1) / BK;
    // prologue: tile 0
    LOAD_A(pa0, 0, 0);
    LOAD_A(pa1, 0, 8);
    LOAD_B(pb0, 0, 0);
    LOAD_B(pb1, 0, 8);
    STS_TILE(0);
    __syncthreads();

    int cur = 0;
    for (int t = 1; t <= numT; t++) {
        if (t < numT) {
            int k0 = t * BK;
            LOAD_A(pa0, k0, 0);
            LOAD_A(pa1, k0, 8);
            LOAD_B(pb0, k0, 0);
            LOAD_B(pb1, k0, 8);
        }
        // compute current stage
#pragma unroll
        for (int kk = 0; kk < BK; kk++) {
            float4 a0 = *(const float4*)&As[cur][kk][ty * 8];
            float4 a1 = *(const float4*)&As[cur][kk][ty * 8 + 4];
            float4 b0 = *(const float4*)&Bs[cur][kk][tx * 8];
            float4 b1 = *(const float4*)&Bs[cur][kk][tx * 8 + 4];
            float2 bb[4];
            bb[0] = make_float2(b0.x, b0.y);
            bb[1] = make_float2(b0.z, b0.w);
            bb[2] = make_float2(b1.x, b1.y);
            bb[3] = make_float2(b1.z, b1.w);
            float av[8] = {a0.x, a0.y, a0.z, a0.w, a1.x, a1.y, a1.z, a1.w};
#pragma unroll
            for (int i = 0; i < 8; i++) {
                float2 ai = make_float2(av[i], av[i]);
#pragma unroll
                for (int j = 0; j < 4; j++) ffma2(acc2[i][j], ai, bb[j]);
            }
        }
        if (t < numT) {
            STS_TILE(cur ^ 1);
            __syncthreads();
            cur ^= 1;
        }
    }
#undef LOAD_A
#undef LOAD_B
#undef STS_TILE

#pragma unroll
    for (int i = 0; i < 8; i++) {
        int r = rowBase + ty * 8 + i;
        if (r >= M) continue;
        float* crow = C + (size_t)r * N;
        float vals[8] = {acc2[i][0].x, acc2[i][0].y, acc2[i][1].x, acc2[i][1].y,
                         acc2[i][2].x, acc2[i][2].y, acc2[i][3].x, acc2[i][3].y};
#pragma unroll
        for (int j = 0; j < 8; j++) {
            int c = colBase + tx * 8 + j;
            if (c < N) {
                float v = vals[j];
                if (reluOut) v = fmaxf(v, 0.f);
                crow[c] = v;
            }
        }
    }
}

// ---------------- SpMM width-500 (float4 gather): out[r,:] = sum val*in[col,:] ---
__global__ void __launch_bounds__(128)
k_spmm_w500(const float* __restrict__ Min, float* __restrict__ Mout, int relu) {
    const int W = 500;
    int r = blockIdx.x;
    int t = threadIdx.x;  // 128; t<125 handles float4 at col 4t
    int start = g_rowptr[r], end = g_rowptr[r + 1];
    float4 acc = make_float4(0.f, 0.f, 0.f, 0.f);
    __shared__ int scol[128];
    __shared__ float sval[128];
    for (int e0 = start; e0 < end; e0 += 128) {
        int n = min(128, end - e0);
        if (t < n) {
            scol[t] = g_cols[e0 + t];
            sval[t] = g_vals[e0 + t];
        }
        __syncthreads();
        if (t < 125) {
            for (int i = 0; i < n; i++) {
                const float4* p = (const float4*)(Min + (size_t)scol[i] * W) + t;
                float v = sval[i];
                float4 x = *p;
                acc.x += v * x.x;
                acc.y += v * x.y;
                acc.z += v * x.z;
                acc.w += v * x.w;
            }
        }
        __syncthreads();
    }
    if (t < 125) {
        if (relu) {
            acc.x = fmaxf(acc.x, 0.f);
            acc.y = fmaxf(acc.y, 0.f);
            acc.z = fmaxf(acc.z, 0.f);
            acc.w = fmaxf(acc.w, 0.f);
        }
        *((float4*)(Mout + (size_t)r * W) + t) = acc;
    }
}

// ---------------- SpMM width-10 (thread per row) --------------------------------
__global__ void k_spmm_w10(const float* __restrict__ Min, float* __restrict__ Mout,
                           int relu) {
    int r = blockIdx.x * blockDim.x + threadIdx.x;
    if (r >= NNODES) return;
    float acc[10];
#pragma unroll
    for (int j = 0; j < 10; j++) acc[j] = 0.f;
    int start = g_rowptr[r], end = g_rowptr[r + 1];
    for (int e = start; e < end; e++) {
        int c = g_cols[e];
        float v = g_vals[e];
        const float2* p = (const float2*)(Min + (size_t)c * 10);
#pragma unroll
        for (int j = 0; j < 5; j++) {
            float2 x = p[j];
            acc[2 * j + 0] += v * x.x;
            acc[2 * j + 1] += v * x.y;
        }
    }
    float* o = Mout + (size_t)r * 10;
#pragma unroll
    for (int j = 0; j < 10; j++) o[j] = relu ? fmaxf(acc[j], 0.f) : acc[j];
}

// ---------------- elementwise mix: O = 0.5*(A+B), n multiple of 4 ----------------
__global__ void k_mix(const float* __restrict__ A, const float* __restrict__ B,
                      float* __restrict__ O, int n4) {
    for (int i = blockIdx.x * blockDim.x + threadIdx.x; i < n4;
         i += gridDim.x * blockDim.x) {
        float4 a = ((const float4*)A)[i];
        float4 b = ((const float4*)B)[i];
        float4 o;
        o.x = 0.5f * (a.x + b.x);
        o.y = 0.5f * (a.y + b.y);
        o.z = 0.5f * (a.z + b.z);
        o.w = 0.5f * (a.w + b.w);
        ((float4*)O)[i] = o;
    }
}

// ---------------- thin GEMM layer4: (0.5*(H+tra3))[50000,2000] @ W4[2000,10] -----
__global__ void __launch_bounds__(256)
k_gemm_thin(const float* __restrict__ Hin, const float* __restrict__ Tmix,
            const float* __restrict__ W4, float* __restrict__ Mout) {
    const int K = 2000, CHUNK = 1000;
    __shared__ float Ws[CHUNK * 10];  // 40 KB
    int tid = threadIdx.x;
    int r = blockIdx.x * 256 + tid;
    float acc[10];
#pragma unroll
    for (int j = 0; j < 10; j++) acc[j] = 0.f;
    for (int k0 = 0; k0 < K; k0 += CHUNK) {
        __syncthreads();
        for (int i = tid; i < CHUNK * 10; i += 256) Ws[i] = W4[k0 * 10 + i];
        __syncthreads();
        if (r < NNODES) {
            const float* hrow = Hin + (size_t)r * K + k0;
            const float* trow = Tmix + (size_t)r * K + k0;
            for (int k = 0; k < CHUNK; k += 4) {
                float4 h = *(const float4*)(hrow + k);
                float4 t = *(const float4*)(trow + k);
                float a0 = 0.5f * (h.x + t.x);
                float a1 = 0.5f * (h.y + t.y);
                float a2 = 0.5f * (h.z + t.z);
                float a3 = 0.5f * (h.w + t.w);
#pragma unroll
                for (int j = 0; j < 10; j++)
                    acc[j] += a0 * Ws[(k + 0) * 10 + j] + a1 * Ws[(k + 1) * 10 + j] +
                              a2 * Ws[(k + 2) * 10 + j] + a3 * Ws[(k + 3) * 10 + j];
            }
        }
    }
    if (r < NNODES) {
        float* o = Mout + (size_t)r * 10;
#pragma unroll
        for (int j = 0; j < 10; j++) o[j] = acc[j];
    }
}

// ---------------- tiny GEMM layer5: (0.5*(H+z))[*,10] @ W5[10,10] ----------------
__global__ void k_gemm5(const float* __restrict__ Hin, const float* __restrict__ Zmix,
                        const float* __restrict__ W5, float* __restrict__ Mout) {
    __shared__ float Ws[100];
    int t = threadIdx.x;
    if (t < 100) Ws[t] = W5[t];
    __syncthreads();
    int r = blockIdx.x * blockDim.x + t;
    if (r >= NNODES) return;
    float a[10];
#pragma unroll
    for (int k = 0; k < 10; k++)
        a[k] = 0.5f * (Hin[(size_t)r * 10 + k] + Zmix[(size_t)r * 10 + k]);
    float* o = Mout + (size_t)r * 10;
#pragma unroll
    for (int j = 0; j < 10; j++) {
        float s = 0.f;
#pragma unroll
        for (int k = 0; k < 10; k++) s += a[k] * Ws[k * 10 + j];
        o[j] = s;
    }
}

// ---------------- row softmax over width 10 --------------------------------------
__global__ void k_softmax(const float* __restrict__ S, float* __restrict__ out) {
    int r = blockIdx.x * blockDim.x + threadIdx.x;
    if (r >= NNODES) return;
    float v[10];
    float m = -1e30f;
#pragma unroll
    for (int j = 0; j < 10; j++) {
        v[j] = S[(size_t)r * 10 + j];
        m = fmaxf(m, v[j]);
    }
    float sum = 0.f;
#pragma unroll
    for (int j = 0; j < 10; j++) {
        v[j] = expf(v[j] - m);
        sum += v[j];
    }
    float inv = 1.f / sum;
#pragma unroll
    for (int j = 0; j < 10; j++) out[(size_t)r * 10 + j] = v[j] * inv;
}

// ---------------- launch ---------------------------------------------------------
extern "C" void kernel_launch(void* const* d_in, const int* in_sizes, int n_in,
                              void* d_out, int out_size) {
    const float* x    = (const float*)d_in[0];   // [50000,512]
    const float* tra1 = (const float*)d_in[1];   // [50000,500]
    const float* tra2 = (const float*)d_in[2];   // [50000,500]
    const float* tra3 = (const float*)d_in[3];   // [50000,2000]
    const float* z    = (const float*)d_in[4];   // [50000,10]
    const float* evals = (const float*)d_in[5];  // [E]
    const int*   row  = (const int*)d_in[6];     // [E]
    const int*   col  = (const int*)d_in[7];     // [E]
    const float* W1 = (const float*)d_in[8];     // [512,500]
    const float* W2 = (const float*)d_in[9];     // [500,500]
    const float* W3 = (const float*)d_in[10];    // [500,2000]
    const float* W4 = (const float*)d_in[11];    // [2000,10]
    const float* W5 = (const float*)d_in[12];    // [10,10]
    float* out = (float*)d_out;

    float *bufA, *bufB, *bufS0, *bufS1;
    cudaGetSymbolAddress((void**)&bufA, g_bufA);
    cudaGetSymbolAddress((void**)&bufB, g_bufB);
    cudaGetSymbolAddress((void**)&bufS0, g_bufS0);
    cudaGetSymbolAddress((void**)&bufS1, g_bufS1);

    dim3 g500(4, 391), g2000(16, 391);

    // CSR build interleaved with L1 GEMM (GEMM doesn't need CSR; also places the
    // big SGEMM at the launch slot ncu has been capturing).
    k_zero_counts<<<64, 256>>>();
    k_hist<<<2048, 256>>>(row);
    k_scan<<<1, 1024>>>();

    // L1: B1 = x @ W1  (4th launch — ncu capture target)
    k_sgemm<<<g500, 256>>>(x, x, W1, bufA, NNODES, 500, 512, 0, 0);

    k_reset_cursor<<<64, 256>>>();
    k_scatter<<<2048, 256>>>(row, col, evals);

    // H1 = relu(spmm(B1))
    k_spmm_w500<<<NNODES, 128>>>(bufA, bufB, 1);

    // L2: B2 = (0.5*(H1+tra1)) @ W2 ; H2 = relu(spmm(B2))
    k_sgemm<<<g500, 256>>>(bufB, tra1, W2, bufA, NNODES, 500, 500, 1, 0);
    k_spmm_w500<<<NNODES, 128>>>(bufA, bufB, 1);

    // L3 (reordered: spmm first at width 500, then GEMM to 2000)
    k_mix<<<2048, 256>>>(bufB, tra2, bufA, NNODES * 500 / 4);
    k_spmm_w500<<<NNODES, 128>>>(bufA, bufB, 0);
    k_sgemm<<<g2000, 256>>>(bufB, bufB, W3, bufA, NNODES, 2000, 500, 0, 1);

    // L4: B4 = (0.5*(H3+tra3)) @ W4 ; H4 = relu(spmm10(B4))
    k_gemm_thin<<<(NNODES + 255) / 256, 256>>>(bufA, tra3, W4, bufS0);
    k_spmm_w10<<<(NNODES + 255) / 256, 256>>>(bufS0, bufS1, 1);

    // L5: B5 = (0.5*(H4+z)) @ W5 ; S5 = spmm10(B5) ; out = softmax(S5)
    k_gemm5<<<(NNODES + 255) / 256, 256>>>(bufS1, z, W5, bufS0);
    k_spmm_w10<<<(NNODES + 255) / 256, 256>>>(bufS0, bufS1, 0);
    k_softmax<<<(NNODES + 255) / 256, 256>>>(bufS1, out);
}

// round 10
// speedup vs baseline: 1.9507x; 1.9507x over previous
#include <cuda_runtime.h>
#include <cuda_bf16.h>
#include <math.h>
#include <stdint.h>

#define NNODES 50000
#define NEDGES 1600000
#define MPAD 50048     // 391 * 128
#define KP 512         // padded K for all big GEMMs
#define NPMAX 2048     // padded N max (L3)

// ---------------- scratch (static device globals; no allocation) ----------------
__device__ float g_bufA[(size_t)NNODES * 2000];   // 400 MB
__device__ float g_bufB[(size_t)NNODES * 2000];   // 400 MB
__device__ float g_bufS0[NNODES * 10];
__device__ float g_bufS1[NNODES * 10];
__device__ int   g_rowptr[NNODES + 1];
__device__ int   g_cursor[NNODES + 1];
__device__ int   g_cols[NEDGES];
__device__ float g_vals[NEDGES];
// bf16-split staging
__device__ __nv_bfloat16 g_Ahi[(size_t)MPAD * KP];   // 51.2 MB
__device__ __nv_bfloat16 g_Alo[(size_t)MPAD * KP];
__device__ __nv_bfloat16 g_Bhi[(size_t)NPMAX * KP];  // 2 MB
__device__ __nv_bfloat16 g_Blo[(size_t)NPMAX * KP];

// ---------------- PTX helpers (base sm_103-safe: ldmatrix + mma.sync) -----------
__device__ __forceinline__ uint32_t smem_u32(const void* p) {
    uint32_t a;
    asm("{ .reg .u64 t; cvta.to.shared.u64 t, %1; cvt.u32.u64 %0, t; }"
        : "=r"(a) : "l"(p));
    return a;
}
#define LDSM4(r, addr)                                                          \
    asm volatile("ldmatrix.sync.aligned.m8n8.x4.shared.b16 {%0,%1,%2,%3}, [%4];" \
                 : "=r"((r)[0]), "=r"((r)[1]), "=r"((r)[2]), "=r"((r)[3])       \
                 : "r"(addr))
#define LDSM2(r, addr)                                                          \
    asm volatile("ldmatrix.sync.aligned.m8n8.x2.shared.b16 {%0,%1}, [%2];"      \
                 : "=r"((r)[0]), "=r"((r)[1])                                   \
                 : "r"(addr))
#define MMA_BF16(d, a, b)                                                       \
    asm volatile(                                                               \
        "mma.sync.aligned.m16n8k16.row.col.f32.bf16.bf16.f32 "                  \
        "{%0,%1,%2,%3}, {%4,%5,%6,%7}, {%8,%9}, {%0,%1,%2,%3};"                 \
        : "+f"((d)[0]), "+f"((d)[1]), "+f"((d)[2]), "+f"((d)[3])                \
        : "r"((a)[0]), "r"((a)[1]), "r"((a)[2]), "r"((a)[3]),                   \
          "r"((b)[0]), "r"((b)[1]))

// ---------------- CSR build --------------------------------------------------
__global__ void k_zero_counts() {
    for (int i = blockIdx.x * blockDim.x + threadIdx.x; i <= NNODES;
         i += gridDim.x * blockDim.x)
        g_cursor[i] = 0;
}
__global__ void k_hist(const int* __restrict__ row) {
    for (int e = blockIdx.x * blockDim.x + threadIdx.x; e < NEDGES;
         e += gridDim.x * blockDim.x)
        atomicAdd(&g_cursor[row[e]], 1);
}
__global__ void k_scan() {
    __shared__ int s[1024];
    const int CH = (NNODES + 1023) / 1024;
    int t = threadIdx.x;
    int beg = t * CH;
    int end = min(NNODES, beg + CH);
    int mysum = 0;
    for (int i = beg; i < end; i++) mysum += g_cursor[i];
    s[t] = mysum;
    __syncthreads();
    for (int off = 1; off < 1024; off <<= 1) {
        int v = (t >= off) ? s[t - off] : 0;
        __syncthreads();
        s[t] += v;
        __syncthreads();
    }
    int run = s[t] - mysum;
    for (int i = beg; i < end; i++) {
        g_rowptr[i] = run;
        run += g_cursor[i];
    }
    if (t == 1023) g_rowptr[NNODES] = s[1023];
}
__global__ void k_reset_cursor() {
    for (int i = blockIdx.x * blockDim.x + threadIdx.x; i <= NNODES;
         i += gridDim.x * blockDim.x)
        g_cursor[i] = g_rowptr[i];
}
__global__ void k_scatter(const int* __restrict__ row, const int* __restrict__ col,
                          const float* __restrict__ vals) {
    for (int e = blockIdx.x * blockDim.x + threadIdx.x; e < NEDGES;
         e += gridDim.x * blockDim.x) {
        int p = atomicAdd(&g_cursor[row[e]], 1);
        g_cols[p] = col[e];
        g_vals[p] = vals[e];
    }
}

// ---------------- bf16 split converts ---------------------------------------
__global__ void k_convA(const float* __restrict__ src, const float* __restrict__ mix,
                        int M, int K) {
    int idx = blockIdx.x * blockDim.x + threadIdx.x;
    int m = idx >> 8;               // KP/2 = 256 pairs per row
    int k2 = (idx & 255) * 2;
    if (m >= MPAD) return;
    float v0 = 0.f, v1 = 0.f;
    if (m < M) {
        if (k2 < K) v0 = src[(size_t)m * K + k2];
        if (k2 + 1 < K) v1 = src[(size_t)m * K + k2 + 1];
        if (mix) {
            if (k2 < K) v0 = 0.5f * (v0 + mix[(size_t)m * K + k2]);
            if (k2 + 1 < K) v1 = 0.5f * (v1 + mix[(size_t)m * K + k2 + 1]);
        }
    }
    __nv_bfloat16 h0 = __float2bfloat16(v0);
    __nv_bfloat16 h1 = __float2bfloat16(v1);
    __nv_bfloat16 l0 = __float2bfloat16(v0 - __bfloat162float(h0));
    __nv_bfloat16 l1 = __float2bfloat16(v1 - __bfloat162float(h1));
    size_t o = ((size_t)m * KP + k2) >> 1;
    __nv_bfloat162* ph = (__nv_bfloat162*)g_Ahi;
    __nv_bfloat162* pl = (__nv_bfloat162*)g_Alo;
    ph[o] = __nv_bfloat162(h0, h1);
    pl[o] = __nv_bfloat162(l0, l1);
}

// B: W [K,N] fp32 -> Bhi/Blo [NP, KP] (transposed, K-major), zero padded.
__global__ void k_convB(const float* __restrict__ W, int K, int N, int NP) {
    int idx = blockIdx.x * blockDim.x + threadIdx.x;
    int n = idx >> 9;  // / KP
    int k = idx & (KP - 1);
    if (n >= NP) return;
    float v = (n < N && k < K) ? W[(size_t)k * N + n] : 0.f;
    __nv_bfloat16 h = __float2bfloat16(v);
    __nv_bfloat16 l = __float2bfloat16(v - __bfloat162float(h));
    g_Bhi[(size_t)n * KP + k] = h;
    g_Blo[(size_t)n * KP + k] = l;
}

// ---------------- HMMA bf16x3 GEMM: C[M,N] = A[M,K] @ W[K,N] ------------------
// Block 128x64, BK=32, 4 warps (2M x 2N), warp tile 64x32, mma m16n8k16.
// 3 products: Ahi*Bhi + Ahi*Blo + Alo*Bhi, fp32 accum.
#define GBM 128
#define GBN 64
#define PADK 40

__global__ void __launch_bounds__(128, 3)
k_mma(const __nv_bfloat16* __restrict__ Ahi, const __nv_bfloat16* __restrict__ Alo,
      const __nv_bfloat16* __restrict__ Bhi, const __nv_bfloat16* __restrict__ Blo,
      float* __restrict__ C, int Mact, int Nact, int relu) {
    __shared__ __nv_bfloat16 sAhi[GBM][PADK];
    __shared__ __nv_bfloat16 sAlo[GBM][PADK];
    __shared__ __nv_bfloat16 sBhi[GBN][PADK];
    __shared__ __nv_bfloat16 sBlo[GBN][PADK];

    int tid = threadIdx.x, lane = tid & 31, w = tid >> 5;
    int wm = w >> 1, wn = w & 1;
    int rowBase = blockIdx.y * GBM, colBase = blockIdx.x * GBN;

    float acc[4][4][4];
#pragma unroll
    for (int i = 0; i < 4; i++)
#pragma unroll
        for (int j = 0; j < 4; j++)
#pragma unroll
            for (int c = 0; c < 4; c++) acc[i][j][c] = 0.f;

    // ldmatrix addresses (fixed per thread)
    int arow = lane & 15;
    int acolH = (lane >> 4) * 8;            // 0 or 8
    int l16 = lane & 15;
    int brow = l16 & 7;
    int bcolH = (l16 >> 3) * 8;             // 0 or 8

    for (int ch = 0; ch < 16; ch++) {
        int k0 = ch * 32;
        // ---- load A tiles: 128 rows x 4 uint4 each (hi & lo) ----
#pragma unroll
        for (int it = 0; it < 4; it++) {
            int i = it * 128 + tid;        // 0..511
            int r = i >> 2, kc = i & 3;
            size_t go = (size_t)(rowBase + r) * KP + k0 + kc * 8;
            *(uint4*)&sAhi[r][kc * 8] = *(const uint4*)(Ahi + go);
            *(uint4*)&sAlo[r][kc * 8] = *(const uint4*)(Alo + go);
        }
        // ---- load B tiles: 64 rows x 4 uint4 each ----
#pragma unroll
        for (int it = 0; it < 2; it++) {
            int i = it * 128 + tid;        // 0..255
            int r = i >> 2, kc = i & 3;
            size_t go = (size_t)(colBase + r) * KP + k0 + kc * 8;
            *(uint4*)&sBhi[r][kc * 8] = *(const uint4*)(Bhi + go);
            *(uint4*)&sBlo[r][kc * 8] = *(const uint4*)(Blo + go);
        }
        __syncthreads();
#pragma unroll
        for (int kk = 0; kk < 2; kk++) {
            int kbase = kk * 16;
            uint32_t ah[4][4], al[4][4], bh[4][2], bl[4][2];
#pragma unroll
            for (int mt = 0; mt < 4; mt++) {
                int r = wm * 64 + mt * 16 + arow;
                uint32_t addr = smem_u32(&sAhi[r][kbase + acolH]);
                LDSM4(ah[mt], addr);
                addr = smem_u32(&sAlo[r][kbase + acolH]);
                LDSM4(al[mt], addr);
            }
#pragma unroll
            for (int nt = 0; nt < 4; nt++) {
                int r = wn * 32 + nt * 8 + brow;
                uint32_t addr = smem_u32(&sBhi[r][kbase + bcolH]);
                LDSM2(bh[nt], addr);
                addr = smem_u32(&sBlo[r][kbase + bcolH]);
                LDSM2(bl[nt], addr);
            }
#pragma unroll
            for (int mt = 0; mt < 4; mt++)
#pragma unroll
                for (int nt = 0; nt < 4; nt++) {
                    MMA_BF16(acc[mt][nt], ah[mt], bh[nt]);
                    MMA_BF16(acc[mt][nt], ah[mt], bl[nt]);
                    MMA_BF16(acc[mt][nt], al[mt], bh[nt]);
                }
        }
        __syncthreads();
    }
    // ---- epilogue ----
#pragma unroll
    for (int mt = 0; mt < 4; mt++) {
#pragma unroll
        for (int nt = 0; nt < 4; nt++) {
            int r0 = rowBase + wm * 64 + mt * 16 + (lane >> 2);
            int c0 = colBase + wn * 32 + nt * 8 + (lane & 3) * 2;
            float* a = acc[mt][nt];
            if (relu) {
                a[0] = fmaxf(a[0], 0.f);
                a[1] = fmaxf(a[1], 0.f);
                a[2] = fmaxf(a[2], 0.f);
                a[3] = fmaxf(a[3], 0.f);
            }
            if (r0 < Mact && c0 + 1 < Nact)
                *(float2*)(C + (size_t)r0 * Nact + c0) = make_float2(a[0], a[1]);
            else if (r0 < Mact && c0 < Nact)
                C[(size_t)r0 * Nact + c0] = a[0];
            int r1 = r0 + 8;
            if (r1 < Mact && c0 + 1 < Nact)
                *(float2*)(C + (size_t)r1 * Nact + c0) = make_float2(a[2], a[3]);
            else if (r1 < Mact && c0 < Nact)
                C[(size_t)r1 * Nact + c0] = a[2];
        }
    }
}

// ---------------- SpMM width-500 (float4 gather) ------------------------------
__global__ void __launch_bounds__(128)
k_spmm_w500(const float* __restrict__ Min, float* __restrict__ Mout, int relu) {
    const int W = 500;
    int r = blockIdx.x;
    int t = threadIdx.x;
    int start = g_rowptr[r], end = g_rowptr[r + 1];
    float4 acc = make_float4(0.f, 0.f, 0.f, 0.f);
    __shared__ int scol[128];
    __shared__ float sval[128];
    for (int e0 = start; e0 < end; e0 += 128) {
        int n = min(128, end - e0);
        if (t < n) {
            scol[t] = g_cols[e0 + t];
            sval[t] = g_vals[e0 + t];
        }
        __syncthreads();
        if (t < 125) {
            for (int i = 0; i < n; i++) {
                const float4* p = (const float4*)(Min + (size_t)scol[i] * W) + t;
                float v = sval[i];
                float4 x = *p;
                acc.x += v * x.x;
                acc.y += v * x.y;
                acc.z += v * x.z;
                acc.w += v * x.w;
            }
        }
        __syncthreads();
    }
    if (t < 125) {
        if (relu) {
            acc.x = fmaxf(acc.x, 0.f);
            acc.y = fmaxf(acc.y, 0.f);
            acc.z = fmaxf(acc.z, 0.f);
            acc.w = fmaxf(acc.w, 0.f);
        }
        *((float4*)(Mout + (size_t)r * W) + t) = acc;
    }
}

// ---------------- SpMM width-10 -----------------------------------------------
__global__ void k_spmm_w10(const float* __restrict__ Min, float* __restrict__ Mout,
                           int relu) {
    int r = blockIdx.x * blockDim.x + threadIdx.x;
    if (r >= NNODES) return;
    float acc[10];
#pragma unroll
    for (int j = 0; j < 10; j++) acc[j] = 0.f;
    int start = g_rowptr[r], end = g_rowptr[r + 1];
    for (int e = start; e < end; e++) {
        int c = g_cols[e];
        float v = g_vals[e];
        const float2* p = (const float2*)(Min + (size_t)c * 10);
#pragma unroll
        for (int j = 0; j < 5; j++) {
            float2 x = p[j];
            acc[2 * j + 0] += v * x.x;
            acc[2 * j + 1] += v * x.y;
        }
    }
    float* o = Mout + (size_t)r * 10;
#pragma unroll
    for (int j = 0; j < 10; j++) o[j] = relu ? fmaxf(acc[j], 0.f) : acc[j];
}

// ---------------- elementwise mix ----------------------------------------------
__global__ void k_mix(const float* __restrict__ A, const float* __restrict__ B,
                      float* __restrict__ O, int n4) {
    for (int i = blockIdx.x * blockDim.x + threadIdx.x; i < n4;
         i += gridDim.x * blockDim.x) {
        float4 a = ((const float4*)A)[i];
        float4 b = ((const float4*)B)[i];
        float4 o;
        o.x = 0.5f * (a.x + b.x);
        o.y = 0.5f * (a.y + b.y);
        o.z = 0.5f * (a.z + b.z);
        o.w = 0.5f * (a.w + b.w);
        ((float4*)O)[i] = o;
    }
}

// ---------------- thin GEMM layer4 ----------------------------------------------
__global__ void __launch_bounds__(256)
k_gemm_thin(const float* __restrict__ Hin, const float* __restrict__ Tmix,
            const float* __restrict__ W4, float* __restrict__ Mout) {
    const int K = 2000, CHUNK = 1000;
    __shared__ float Ws[CHUNK * 10];
    int tid = threadIdx.x;
    int r = blockIdx.x * 256 + tid;
    float acc[10];
#pragma unroll
    for (int j = 0; j < 10; j++) acc[j] = 0.f;
    for (int k0 = 0; k0 < K; k0 += CHUNK) {
        __syncthreads();
        for (int i = tid; i < CHUNK * 10; i += 256) Ws[i] = W4[k0 * 10 + i];
        __syncthreads();
        if (r < NNODES) {
            const float* hrow = Hin + (size_t)r * K + k0;
            const float* trow = Tmix + (size_t)r * K + k0;
            for (int k = 0; k < CHUNK; k += 4) {
                float4 h = *(const float4*)(hrow + k);
                float4 t = *(const float4*)(trow + k);
                float a0 = 0.5f * (h.x + t.x);
                float a1 = 0.5f * (h.y + t.y);
                float a2 = 0.5f * (h.z + t.z);
                float a3 = 0.5f * (h.w + t.w);
#pragma unroll
                for (int j = 0; j < 10; j++)
                    acc[j] += a0 * Ws[(k + 0) * 10 + j] + a1 * Ws[(k + 1) * 10 + j] +
                              a2 * Ws[(k + 2) * 10 + j] + a3 * Ws[(k + 3) * 10 + j];
            }
        }
    }
    if (r < NNODES) {
        float* o = Mout + (size_t)r * 10;
#pragma unroll
        for (int j = 0; j < 10; j++) o[j] = acc[j];
    }
}

// ---------------- tiny GEMM layer5 ----------------------------------------------
__global__ void k_gemm5(const float* __restrict__ Hin, const float* __restrict__ Zmix,
                        const float* __restrict__ W5, float* __restrict__ Mout) {
    __shared__ float Ws[100];
    int t = threadIdx.x;
    if (t < 100) Ws[t] = W5[t];
    __syncthreads();
    int r = blockIdx.x * blockDim.x + t;
    if (r >= NNODES) return;
    float a[10];
#pragma unroll
    for (int k = 0; k < 10; k++)
        a[k] = 0.5f * (Hin[(size_t)r * 10 + k] + Zmix[(size_t)r * 10 + k]);
    float* o = Mout + (size_t)r * 10;
#pragma unroll
    for (int j = 0; j < 10; j++) {
        float s = 0.f;
#pragma unroll
        for (int k = 0; k < 10; k++) s += a[k] * Ws[k * 10 + j];
        o[j] = s;
    }
}

// ---------------- row softmax over width 10 --------------------------------------
__global__ void k_softmax(const float* __restrict__ S, float* __restrict__ out) {
    int r = blockIdx.x * blockDim.x + threadIdx.x;
    if (r >= NNODES) return;
    float v[10];
    float m = -1e30f;
#pragma unroll
    for (int j = 0; j < 10; j++) {
        v[j] = S[(size_t)r * 10 + j];
        m = fmaxf(m, v[j]);
    }
    float sum = 0.f;
#pragma unroll
    for (int j = 0; j < 10; j++) {
        v[j] = expf(v[j] - m);
        sum += v[j];
    }
    float inv = 1.f / sum;
#pragma unroll
    for (int j = 0; j < 10; j++) out[(size_t)r * 10 + j] = v[j] * inv;
}

// ---------------- launch ---------------------------------------------------------
extern "C" void kernel_launch(void* const* d_in, const int* in_sizes, int n_in,
                              void* d_out, int out_size) {
    const float* x    = (const float*)d_in[0];
    const float* tra1 = (const float*)d_in[1];
    const float* tra2 = (const float*)d_in[2];
    const float* tra3 = (const float*)d_in[3];
    const float* z    = (const float*)d_in[4];
    const float* evals = (const float*)d_in[5];
    const int*   row  = (const int*)d_in[6];
    const int*   col  = (const int*)d_in[7];
    const float* W1 = (const float*)d_in[8];
    const float* W2 = (const float*)d_in[9];
    const float* W3 = (const float*)d_in[10];
    const float* W4 = (const float*)d_in[11];
    const float* W5 = (const float*)d_in[12];
    float* out = (float*)d_out;

    float *bufA, *bufB, *bufS0, *bufS1;
    __nv_bfloat16 *Ahi, *Alo, *Bhi, *Blo;
    cudaGetSymbolAddress((void**)&bufA, g_bufA);
    cudaGetSymbolAddress((void**)&bufB, g_bufB);
    cudaGetSymbolAddress((void**)&bufS0, g_bufS0);
    cudaGetSymbolAddress((void**)&bufS1, g_bufS1);
    cudaGetSymbolAddress((void**)&Ahi, g_Ahi);
    cudaGetSymbolAddress((void**)&Alo, g_Alo);
    cudaGetSymbolAddress((void**)&Bhi, g_Bhi);
    cudaGetSymbolAddress((void**)&Blo, g_Blo);

    const int CONV_A_BLOCKS = MPAD;   // MPAD*256 threads / 256
    const int MT = 391;               // m-tiles

    // L1 prep (no CSR dep) — k_mma is the 4th launch (ncu capture slot)
    k_convA<<<CONV_A_BLOCKS, 256>>>(x, nullptr, NNODES, 512);
    k_convB<<<512 * 512 / 256, 256>>>(W1, 512, 500, 512);
    k_zero_counts<<<64, 256>>>();
    k_mma<<<dim3(8, MT), 128>>>(Ahi, Alo, Bhi, Blo, bufA, NNODES, 500, 0);
    // CSR build
    k_hist<<<2048, 256>>>(row);
    k_scan<<<1, 1024>>>();
    k_reset_cursor<<<64, 256>>>();
    k_scatter<<<2048, 256>>>(row, col, evals);

    // L1: H1 = relu(spmm(B1))
    k_spmm_w500<<<NNODES, 128>>>(bufA, bufB, 1);

    // L2: B2 = (0.5*(H1+tra1)) @ W2 ; H2 = relu(spmm(B2))
    k_convA<<<CONV_A_BLOCKS, 256>>>(bufB, tra1, NNODES, 500);
    k_convB<<<512 * 512 / 256, 256>>>(W2, 500, 500, 512);
    k_mma<<<dim3(8, MT), 128>>>(Ahi, Alo, Bhi, Blo, bufA, NNODES, 500, 0);
    k_spmm_w500<<<NNODES, 128>>>(bufA, bufB, 1);

    // L3: mix -> spmm (width 500) -> GEMM to 2000 with relu
    k_mix<<<2048, 256>>>(bufB, tra2, bufA, NNODES * 500 / 4);
    k_spmm_w500<<<NNODES, 128>>>(bufA, bufB, 0);
    k_convA<<<CONV_A_BLOCKS, 256>>>(bufB, nullptr, NNODES, 500);
    k_convB<<<2048 * 512 / 256, 256>>>(W3, 500, 2000, 2048);
    k_mma<<<dim3(32, MT), 128>>>(Ahi, Alo, Bhi, Blo, bufA, NNODES, 2000, 1);

    // L4: B4 = (0.5*(H3+tra3)) @ W4 ; H4 = relu(spmm10(B4))
    k_gemm_thin<<<(NNODES + 255) / 256, 256>>>(bufA, tra3, W4, bufS0);
    k_spmm_w10<<<(NNODES + 255) / 256, 256>>>(bufS0, bufS1, 1);

    // L5
    k_gemm5<<<(NNODES + 255) / 256, 256>>>(bufS1, z, W5, bufS0);
    k_spmm_w10<<<(NNODES + 255) / 256, 256>>>(bufS0, bufS1, 0);
    k_softmax<<<(NNODES + 255) / 256, 256>>>(bufS1, out);
}

// round 12
// speedup vs baseline: 2.2342x; 1.1454x over previous
#include <cuda_runtime.h>
#include <cuda_bf16.h>
#include <math.h>
#include <stdint.h>

#define NNODES 50000
#define NEDGES 1600000
#define MPAD 50048     // 391 * 128
#define KP 512         // padded K for all big GEMMs
#define NPMAX 2048     // padded N max (L3)

// ---------------- scratch (static device globals; no allocation) ----------------
__device__ float g_bufA[(size_t)NNODES * 2000];   // 400 MB
__device__ float g_bufB[(size_t)NNODES * 2000];   // 400 MB
__device__ float g_bufS0[NNODES * 10];
__device__ float g_bufS1[NNODES * 10];
__device__ int   g_rowptr[NNODES + 1];
__device__ int   g_cursor[NNODES + 1];
__device__ int   g_cols[NEDGES];
__device__ float g_vals[NEDGES];
// bf16-split staging
__device__ __nv_bfloat16 g_Ahi[(size_t)MPAD * KP];   // 51.2 MB
__device__ __nv_bfloat16 g_Alo[(size_t)MPAD * KP];
__device__ __nv_bfloat16 g_Bhi[(size_t)NPMAX * KP];  // 2 MB
__device__ __nv_bfloat16 g_Blo[(size_t)NPMAX * KP];

// ---------------- PTX helpers (base sm_103-safe) --------------------------------
__device__ __forceinline__ uint32_t smem_u32(const void* p) {
    uint32_t a;
    asm("{ .reg .u64 t; cvta.to.shared.u64 t, %1; cvt.u32.u64 %0, t; }"
        : "=r"(a) : "l"(p));
    return a;
}
#define LDSM4(r, addr)                                                          \
    asm volatile("ldmatrix.sync.aligned.m8n8.x4.shared.b16 {%0,%1,%2,%3}, [%4];" \
                 : "=r"((r)[0]), "=r"((r)[1]), "=r"((r)[2]), "=r"((r)[3])       \
                 : "r"(addr))
#define LDSM2(r, addr)                                                          \
    asm volatile("ldmatrix.sync.aligned.m8n8.x2.shared.b16 {%0,%1}, [%2];"      \
                 : "=r"((r)[0]), "=r"((r)[1])                                   \
                 : "r"(addr))
#define MMA_BF16(d, a, b)                                                       \
    asm volatile(                                                               \
        "mma.sync.aligned.m16n8k16.row.col.f32.bf16.bf16.f32 "                  \
        "{%0,%1,%2,%3}, {%4,%5,%6,%7}, {%8,%9}, {%0,%1,%2,%3};"                 \
        : "+f"((d)[0]), "+f"((d)[1]), "+f"((d)[2]), "+f"((d)[3])                \
        : "r"((a)[0]), "r"((a)[1]), "r"((a)[2]), "r"((a)[3]),                   \
          "r"((b)[0]), "r"((b)[1]))
#define CP_ASYNC16(saddr, gptr)                                                 \
    asm volatile("cp.async.cg.shared.global [%0], [%1], 16;" ::                 \
                 "r"(saddr), "l"(gptr))
#define CP_COMMIT() asm volatile("cp.async.commit_group;" ::: "memory")
#define CP_WAIT(n) asm volatile("cp.async.wait_group %0;" :: "n"(n) : "memory")

// ---------------- CSR build --------------------------------------------------
__global__ void k_zero_counts() {
    for (int i = blockIdx.x * blockDim.x + threadIdx.x; i <= NNODES;
         i += gridDim.x * blockDim.x)
        g_cursor[i] = 0;
}
__global__ void k_hist(const int* __restrict__ row) {
    for (int e = blockIdx.x * blockDim.x + threadIdx.x; e < NEDGES;
         e += gridDim.x * blockDim.x)
        atomicAdd(&g_cursor[row[e]], 1);
}
__global__ void k_scan() {
    __shared__ int s[1024];
    const int CH = (NNODES + 1023) / 1024;
    int t = threadIdx.x;
    int beg = t * CH;
    int end = min(NNODES, beg + CH);
    int mysum = 0;
    for (int i = beg; i < end; i++) mysum += g_cursor[i];
    s[t] = mysum;
    __syncthreads();
    for (int off = 1; off < 1024; off <<= 1) {
        int v = (t >= off) ? s[t - off] : 0;
        __syncthreads();
        s[t] += v;
        __syncthreads();
    }
    int run = s[t] - mysum;
    for (int i = beg; i < end; i++) {
        g_rowptr[i] = run;
        run += g_cursor[i];
    }
    if (t == 1023) g_rowptr[NNODES] = s[1023];
}
__global__ void k_reset_cursor() {
    for (int i = blockIdx.x * blockDim.x + threadIdx.x; i <= NNODES;
         i += gridDim.x * blockDim.x)
        g_cursor[i] = g_rowptr[i];
}
__global__ void k_scatter(const int* __restrict__ row, const int* __restrict__ col,
                          const float* __restrict__ vals) {
    for (int e = blockIdx.x * blockDim.x + threadIdx.x; e < NEDGES;
         e += gridDim.x * blockDim.x) {
        int p = atomicAdd(&g_cursor[row[e]], 1);
        g_cols[p] = col[e];
        g_vals[p] = vals[e];
    }
}

// ---------------- bf16 split converts ---------------------------------------
// A: op rows [M,K] (+optional mix) -> Ahi/Alo [MPAD, KP], zero padded.
__global__ void k_convA(const float* __restrict__ src, const float* __restrict__ mix,
                        int M, int K) {
    int idx = blockIdx.x * blockDim.x + threadIdx.x;
    int m = idx >> 8;               // KP/2 = 256 pairs per row
    int k2 = (idx & 255) * 2;
    if (m >= MPAD) return;
    float v0 = 0.f, v1 = 0.f;
    if (m < M) {
        if (k2 < K) v0 = src[(size_t)m * K + k2];
        if (k2 + 1 < K) v1 = src[(size_t)m * K + k2 + 1];
        if (mix) {
            if (k2 < K) v0 = 0.5f * (v0 + mix[(size_t)m * K + k2]);
            if (k2 + 1 < K) v1 = 0.5f * (v1 + mix[(size_t)m * K + k2 + 1]);
        }
    }
    __nv_bfloat16 h0 = __float2bfloat16(v0);
    __nv_bfloat16 h1 = __float2bfloat16(v1);
    __nv_bfloat16 l0 = __float2bfloat16(v0 - __bfloat162float(h0));
    __nv_bfloat16 l1 = __float2bfloat16(v1 - __bfloat162float(h1));
    size_t o = ((size_t)m * KP + k2) >> 1;
    __nv_bfloat162* ph = (__nv_bfloat162*)g_Ahi;
    __nv_bfloat162* pl = (__nv_bfloat162*)g_Alo;
    ph[o] = __nv_bfloat162(h0, h1);
    pl[o] = __nv_bfloat162(l0, l1);
}

// B: W [K,N] fp32 -> Bhi/Blo [NP, KP] (transposed, K-major), zero padded.
__global__ void k_convB(const float* __restrict__ W, int K, int N, int NP) {
    int idx = blockIdx.x * blockDim.x + threadIdx.x;
    int n = idx >> 9;  // / KP
    int k = idx & (KP - 1);
    if (n >= NP) return;
    float v = (n < N && k < K) ? W[(size_t)k * N + n] : 0.f;
    __nv_bfloat16 h = __float2bfloat16(v);
    __nv_bfloat16 l = __float2bfloat16(v - __bfloat162float(h));
    g_Bhi[(size_t)n * KP + k] = h;
    g_Blo[(size_t)n * KP + k] = l;
}

// ---------------- HMMA bf16x3 GEMM, cp.async double-buffered ------------------
// Block 128x64, BK=32, 4 warps (2M x 2N), warp tile 64x32, mma m16n8k16.
#define GBM 128
#define GBN 64
#define PADK 40
// dynamic smem offsets (bytes); stage strides
#define SA_STG 10240   // 128*40*2
#define SB_STG 5120    // 64*40*2
#define OFF_AHI 0
#define OFF_ALO 20480
#define OFF_BHI 40960
#define OFF_BLO 51200
#define SM_TOTAL 61440

__global__ void __launch_bounds__(128, 3)
k_mma(const __nv_bfloat16* __restrict__ Ahi, const __nv_bfloat16* __restrict__ Alo,
      const __nv_bfloat16* __restrict__ Bhi, const __nv_bfloat16* __restrict__ Blo,
      float* __restrict__ C, int Mact, int Nact, int relu) {
    extern __shared__ char smem[];
    uint32_t sb = smem_u32(smem);

    int tid = threadIdx.x, lane = tid & 31, w = tid >> 5;
    int wm = w >> 1, wn = w & 1;
    int rowBase = blockIdx.y * GBM, colBase = blockIdx.x * GBN;

    float acc[4][4][4];
#pragma unroll
    for (int i = 0; i < 4; i++)
#pragma unroll
        for (int j = 0; j < 4; j++)
#pragma unroll
            for (int c = 0; c < 4; c++) acc[i][j][c] = 0.f;

    int arow = lane & 15;
    int acolH = (lane >> 4) * 8;
    int l16 = lane & 15;
    int brow = l16 & 7;
    int bcolH = (l16 >> 3) * 8;

    // loader indices (fixed): each thread covers A rows via 4 iters, B via 2
    int lr = tid >> 2;        // 0..31
    int lk = (tid & 3) * 16;  // byte offset of 16B chunk within 64B row-span

    // ---- async load of one k-chunk into stage ----
#define LOAD_CHUNK(ch, stg)                                                     \
    {                                                                           \
        int k0 = (ch) * 32;                                                     \
        _Pragma("unroll")                                                       \
        for (int it = 0; it < 4; it++) {                                        \
            int r = it * 32 + lr;                                               \
            const __nv_bfloat16* gh = Ahi + (size_t)(rowBase + r) * KP + k0;    \
            const __nv_bfloat16* gl = Alo + (size_t)(rowBase + r) * KP + k0;    \
            uint32_t so = (stg) * SA_STG + r * 80 + lk;                         \
            CP_ASYNC16(sb + OFF_AHI + so, (const char*)gh + lk);                \
            CP_ASYNC16(sb + OFF_ALO + so, (const char*)gl + lk);                \
        }                                                                       \
        _Pragma("unroll")                                                       \
        for (int it = 0; it < 2; it++) {                                        \
            int r = it * 32 + lr;                                               \
            const __nv_bfloat16* gh = Bhi + (size_t)(colBase + r) * KP + k0;    \
            const __nv_bfloat16* gl = Blo + (size_t)(colBase + r) * KP + k0;    \
            uint32_t so = (stg) * SB_STG + r * 80 + lk;                         \
            CP_ASYNC16(sb + OFF_BHI + so, (const char*)gh + lk);                \
            CP_ASYNC16(sb + OFF_BLO + so, (const char*)gl + lk);                \
        }                                                                       \
    }

    LOAD_CHUNK(0, 0);
    CP_COMMIT();

    for (int ch = 0; ch < 16; ch++) {
        int cur = ch & 1;
        if (ch + 1 < 16) {
            LOAD_CHUNK(ch + 1, cur ^ 1);
            CP_COMMIT();
            CP_WAIT(1);
        } else {
            CP_WAIT(0);
        }
        __syncthreads();
        uint32_t aHiB = sb + OFF_AHI + cur * SA_STG;
        uint32_t aLoB = sb + OFF_ALO + cur * SA_STG;
        uint32_t bHiB = sb + OFF_BHI + cur * SB_STG;
        uint32_t bLoB = sb + OFF_BLO + cur * SB_STG;
#pragma unroll
        for (int kk = 0; kk < 2; kk++) {
            int kbase = kk * 16;
            uint32_t ah[4][4], al[4][4], bh[4][2], bl[4][2];
#pragma unroll
            for (int mt = 0; mt < 4; mt++) {
                uint32_t ro = (wm * 64 + mt * 16 + arow) * 80 +
                              (kbase + acolH) * 2;
                LDSM4(ah[mt], aHiB + ro);
                LDSM4(al[mt], aLoB + ro);
            }
#pragma unroll
            for (int nt = 0; nt < 4; nt++) {
                uint32_t ro = (wn * 32 + nt * 8 + brow) * 80 +
                              (kbase + bcolH) * 2;
                LDSM2(bh[nt], bHiB + ro);
                LDSM2(bl[nt], bLoB + ro);
            }
#pragma unroll
            for (int mt = 0; mt < 4; mt++)
#pragma unroll
                for (int nt = 0; nt < 4; nt++) {
                    MMA_BF16(acc[mt][nt], ah[mt], bh[nt]);
                    MMA_BF16(acc[mt][nt], ah[mt], bl[nt]);
                    MMA_BF16(acc[mt][nt], al[mt], bh[nt]);
                }
        }
        __syncthreads();
    }
#undef LOAD_CHUNK

    // ---- epilogue ----
#pragma unroll
    for (int mt = 0; mt < 4; mt++) {
#pragma unroll
        for (int nt = 0; nt < 4; nt++) {
            int r0 = rowBase + wm * 64 + mt * 16 + (lane >> 2);
            int c0 = colBase + wn * 32 + nt * 8 + (lane & 3) * 2;
            float* a = acc[mt][nt];
            if (relu) {
                a[0] = fmaxf(a[0], 0.f);
                a[1] = fmaxf(a[1], 0.f);
                a[2] = fmaxf(a[2], 0.f);
                a[3] = fmaxf(a[3], 0.f);
            }
            if (r0 < Mact && c0 + 1 < Nact)
                *(float2*)(C + (size_t)r0 * Nact + c0) = make_float2(a[0], a[1]);
            else if (r0 < Mact && c0 < Nact)
                C[(size_t)r0 * Nact + c0] = a[0];
            int r1 = r0 + 8;
            if (r1 < Mact && c0 + 1 < Nact)
                *(float2*)(C + (size_t)r1 * Nact + c0) = make_float2(a[2], a[3]);
            else if (r1 < Mact && c0 < Nact)
                C[(size_t)r1 * Nact + c0] = a[2];
        }
    }
}

// ---------------- SpMM width-500 -> fp32 out, fused relu+mix ------------------
// out = mix ? 0.5*(act(acc)+mix) : act(acc)
__global__ void __launch_bounds__(128)
k_spmm_w500(const float* __restrict__ Min, const float* __restrict__ mix,
            float* __restrict__ Mout, int relu) {
    const int W = 500;
    int r = blockIdx.x;
    int t = threadIdx.x;
    int start = g_rowptr[r], end = g_rowptr[r + 1];
    float4 acc = make_float4(0.f, 0.f, 0.f, 0.f);
    __shared__ int scol[128];
    __shared__ float sval[128];
    for (int e0 = start; e0 < end; e0 += 128) {
        int n = min(128, end - e0);
        if (t < n) {
            scol[t] = g_cols[e0 + t];
            sval[t] = g_vals[e0 + t];
        }
        __syncthreads();
        if (t < 125) {
            for (int i = 0; i < n; i++) {
                const float4* p = (const float4*)(Min + (size_t)scol[i] * W) + t;
                float v = sval[i];
                float4 x = *p;
                acc.x += v * x.x;
                acc.y += v * x.y;
                acc.z += v * x.z;
                acc.w += v * x.w;
            }
        }
        __syncthreads();
    }
    if (t < 125) {
        if (relu) {
            acc.x = fmaxf(acc.x, 0.f);
            acc.y = fmaxf(acc.y, 0.f);
            acc.z = fmaxf(acc.z, 0.f);
            acc.w = fmaxf(acc.w, 0.f);
        }
        if (mix) {
            float4 mx = *((const float4*)(mix + (size_t)r * W) + t);
            acc.x = 0.5f * (acc.x + mx.x);
            acc.y = 0.5f * (acc.y + mx.y);
            acc.z = 0.5f * (acc.z + mx.z);
            acc.w = 0.5f * (acc.w + mx.w);
        }
        *((float4*)(Mout + (size_t)r * W) + t) = acc;
    }
}

// ---------------- SpMM width-500 -> bf16 hi/lo split out, fused relu+mix ------
__global__ void __launch_bounds__(128)
k_spmm_w500_split(const float* __restrict__ Min, const float* __restrict__ mix,
                  int relu) {
    const int W = 500;
    int r = blockIdx.x;
    int t = threadIdx.x;
    int start = g_rowptr[r], end = g_rowptr[r + 1];
    float4 acc = make_float4(0.f, 0.f, 0.f, 0.f);
    __shared__ int scol[128];
    __shared__ float sval[128];
    for (int e0 = start; e0 < end; e0 += 128) {
        int n = min(128, end - e0);
        if (t < n) {
            scol[t] = g_cols[e0 + t];
            sval[t] = g_vals[e0 + t];
        }
        __syncthreads();
        if (t < 125) {
            for (int i = 0; i < n; i++) {
                const float4* p = (const float4*)(Min + (size_t)scol[i] * W) + t;
                float v = sval[i];
                float4 x = *p;
                acc.x += v * x.x;
                acc.y += v * x.y;
                acc.z += v * x.z;
                acc.w += v * x.w;
            }
        }
        __syncthreads();
    }
    __nv_bfloat162* ph = (__nv_bfloat162*)(g_Ahi + (size_t)r * KP);
    __nv_bfloat162* pl = (__nv_bfloat162*)(g_Alo + (size_t)r * KP);
    if (t < 125) {
        if (relu) {
            acc.x = fmaxf(acc.x, 0.f);
            acc.y = fmaxf(acc.y, 0.f);
            acc.z = fmaxf(acc.z, 0.f);
            acc.w = fmaxf(acc.w, 0.f);
        }
        if (mix) {
            float4 mx = *((const float4*)(mix + (size_t)r * W) + t);
            acc.x = 0.5f * (acc.x + mx.x);
            acc.y = 0.5f * (acc.y + mx.y);
            acc.z = 0.5f * (acc.z + mx.z);
            acc.w = 0.5f * (acc.w + mx.w);
        }
        __nv_bfloat16 h0 = __float2bfloat16(acc.x);
        __nv_bfloat16 h1 = __float2bfloat16(acc.y);
        __nv_bfloat16 h2 = __float2bfloat16(acc.z);
        __nv_bfloat16 h3 = __float2bfloat16(acc.w);
        ph[2 * t + 0] = __nv_bfloat162(h0, h1);
        ph[2 * t + 1] = __nv_bfloat162(h2, h3);
        pl[2 * t + 0] = __nv_bfloat162(
            __float2bfloat16(acc.x - __bfloat162float(h0)),
            __float2bfloat16(acc.y - __bfloat162float(h1)));
        pl[2 * t + 1] = __nv_bfloat162(
            __float2bfloat16(acc.z - __bfloat162float(h2)),
            __float2bfloat16(acc.w - __bfloat162float(h3)));
    } else {
        // t = 125..127: zero pad cols 500..511
        __nv_bfloat162 zz(__float2bfloat16(0.f), __float2bfloat16(0.f));
        ph[2 * t + 0] = zz;
        ph[2 * t + 1] = zz;
        pl[2 * t + 0] = zz;
        pl[2 * t + 1] = zz;
    }
}

// ---------------- SpMM width-10 -----------------------------------------------
__global__ void k_spmm_w10(const float* __restrict__ Min, float* __restrict__ Mout,
                           int relu) {
    int r = blockIdx.x * blockDim.x + threadIdx.x;
    if (r >= NNODES) return;
    float acc[10];
#pragma unroll
    for (int j = 0; j < 10; j++) acc[j] = 0.f;
    int start = g_rowptr[r], end = g_rowptr[r + 1];
    for (int e = start; e < end; e++) {
        int c = g_cols[e];
        float v = g_vals[e];
        const float2* p = (const float2*)(Min + (size_t)c * 10);
#pragma unroll
        for (int j = 0; j < 5; j++) {
            float2 x = p[j];
            acc[2 * j + 0] += v * x.x;
            acc[2 * j + 1] += v * x.y;
        }
    }
    float* o = Mout + (size_t)r * 10;
#pragma unroll
    for (int j = 0; j < 10; j++) o[j] = relu ? fmaxf(acc[j], 0.f) : acc[j];
}

// ---------------- thin GEMM layer4 ----------------------------------------------
__global__ void __launch_bounds__(256)
k_gemm_thin(const float* __restrict__ Hin, const float* __restrict__ Tmix,
            const float* __restrict__ W4, float* __restrict__ Mout) {
    const int K = 2000, CHUNK = 1000;
    __shared__ float Ws[CHUNK * 10];
    int tid = threadIdx.x;
    int r = blockIdx.x * 256 + tid;
    float acc[10];
#pragma unroll
    for (int j = 0; j < 10; j++) acc[j] = 0.f;
    for (int k0 = 0; k0 < K; k0 += CHUNK) {
        __syncthreads();
        for (int i = tid; i < CHUNK * 10; i += 256) Ws[i] = W4[k0 * 10 + i];
        __syncthreads();
        if (r < NNODES) {
            const float* hrow = Hin + (size_t)r * K + k0;
            const float* trow = Tmix + (size_t)r * K + k0;
            for (int k = 0; k < CHUNK; k += 4) {
                float4 h = *(const float4*)(hrow + k);
                float4 t = *(const float4*)(trow + k);
                float a0 = 0.5f * (h.x + t.x);
                float a1 = 0.5f * (h.y + t.y);
                float a2 = 0.5f * (h.z + t.z);
                float a3 = 0.5f * (h.w + t.w);
#pragma unroll
                for (int j = 0; j < 10; j++)
                    acc[j] += a0 * Ws[(k + 0) * 10 + j] + a1 * Ws[(k + 1) * 10 + j] +
                              a2 * Ws[(k + 2) * 10 + j] + a3 * Ws[(k + 3) * 10 + j];
            }
        }
    }
    if (r < NNODES) {
        float* o = Mout + (size_t)r * 10;
#pragma unroll
        for (int j = 0; j < 10; j++) o[j] = acc[j];
    }
}

// ---------------- tiny GEMM layer5 ----------------------------------------------
__global__ void k_gemm5(const float* __restrict__ Hin, const float* __restrict__ Zmix,
                        const float* __restrict__ W5, float* __restrict__ Mout) {
    __shared__ float Ws[100];
    int t = threadIdx.x;
    if (t < 100) Ws[t] = W5[t];
    __syncthreads();
    int r = blockIdx.x * blockDim.x + t;
    if (r >= NNODES) return;
    float a[10];
#pragma unroll
    for (int k = 0; k < 10; k++)
        a[k] = 0.5f * (Hin[(size_t)r * 10 + k] + Zmix[(size_t)r * 10 + k]);
    float* o = Mout + (size_t)r * 10;
#pragma unroll
    for (int j = 0; j < 10; j++) {
        float s = 0.f;
#pragma unroll
        for (int k = 0; k < 10; k++) s += a[k] * Ws[k * 10 + j];
        o[j] = s;
    }
}

// ---------------- row softmax over width 10 --------------------------------------
__global__ void k_softmax(const float* __restrict__ S, float* __restrict__ out) {
    int r = blockIdx.x * blockDim.x + threadIdx.x;
    if (r >= NNODES) return;
    float v[10];
    float m = -1e30f;
#pragma unroll
    for (int j = 0; j < 10; j++) {
        v[j] = S[(size_t)r * 10 + j];
        m = fmaxf(m, v[j]);
    }
    float sum = 0.f;
#pragma unroll
    for (int j = 0; j < 10; j++) {
        v[j] = expf(v[j] - m);
        sum += v[j];
    }
    float inv = 1.f / sum;
#pragma unroll
    for (int j = 0; j < 10; j++) out[(size_t)r * 10 + j] = v[j] * inv;
}

// ---------------- launch ---------------------------------------------------------
extern "C" void kernel_launch(void* const* d_in, const int* in_sizes, int n_in,
                              void* d_out, int out_size) {
    const float* x    = (const float*)d_in[0];
    const float* tra1 = (const float*)d_in[1];
    const float* tra2 = (const float*)d_in[2];
    const float* tra3 = (const float*)d_in[3];
    const float* z    = (const float*)d_in[4];
    const float* evals = (const float*)d_in[5];
    const int*   row  = (const int*)d_in[6];
    const int*   col  = (const int*)d_in[7];
    const float* W1 = (const float*)d_in[8];
    const float* W2 = (const float*)d_in[9];
    const float* W3 = (const float*)d_in[10];
    const float* W4 = (const float*)d_in[11];
    const float* W5 = (const float*)d_in[12];
    float* out = (float*)d_out;

    float *bufA, *bufB, *bufS0, *bufS1;
    __nv_bfloat16 *Ahi, *Alo, *Bhi, *Blo;
    cudaGetSymbolAddress((void**)&bufA, g_bufA);
    cudaGetSymbolAddress((void**)&bufB, g_bufB);
    cudaGetSymbolAddress((void**)&bufS0, g_bufS0);
    cudaGetSymbolAddress((void**)&bufS1, g_bufS1);
    cudaGetSymbolAddress((void**)&Ahi, g_Ahi);
    cudaGetSymbolAddress((void**)&Alo, g_Alo);
    cudaGetSymbolAddress((void**)&Bhi, g_Bhi);
    cudaGetSymbolAddress((void**)&Blo, g_Blo);

    cudaFuncSetAttribute(k_mma, cudaFuncAttributeMaxDynamicSharedMemorySize,
                         SM_TOTAL);

    const int CONV_A_BLOCKS = MPAD;
    const int MT = 391;

    // L1 prep (no CSR dep) — k_mma is the 4th launch (ncu capture slot)
    k_convA<<<CONV_A_BLOCKS, 256>>>(x, nullptr, NNODES, 512);
    k_convB<<<512 * 512 / 256, 256>>>(W1, 512, 500, 512);
    k_zero_counts<<<64, 256>>>();
    k_mma<<<dim3(8, MT), 128, SM_TOTAL>>>(Ahi, Alo, Bhi, Blo, bufA, NNODES, 500, 0);
    // CSR build
    k_hist<<<2048, 256>>>(row);
    k_scan<<<1, 1024>>>();
    k_reset_cursor<<<64, 256>>>();
    k_scatter<<<2048, 256>>>(row, col, evals);

    // L1->L2: A2 = split(0.5*(relu(spmm(B1)) + tra1))  (fused)
    k_spmm_w500_split<<<NNODES, 128>>>(bufA, tra1, 1);

    // L2: B2 = A2 @ W2
    k_convB<<<512 * 512 / 256, 256>>>(W2, 500, 500, 512);
    k_mma<<<dim3(8, MT), 128, SM_TOTAL>>>(Ahi, Alo, Bhi, Blo, bufA, NNODES, 500, 0);

    // L2->L3: M3 = 0.5*(relu(spmm(B2)) + tra2)  (fused fp32 out)
    k_spmm_w500<<<NNODES, 128>>>(bufA, tra2, bufB, 1);
    // S3 = spmm(M3), split to bf16 (no relu, no mix)
    k_spmm_w500_split<<<NNODES, 128>>>(bufB, nullptr, 0);

    // L3: H3 = relu(S3 @ W3)
    k_convB<<<2048 * 512 / 256, 256>>>(W3, 500, 2000, 2048);
    k_mma<<<dim3(32, MT), 128, SM_TOTAL>>>(Ahi, Alo, Bhi, Blo, bufA, NNODES, 2000, 1);

    // L4: B4 = (0.5*(H3+tra3)) @ W4 ; H4 = relu(spmm10(B4))
    k_gemm_thin<<<(NNODES + 255) / 256, 256>>>(bufA, tra3, W4, bufS0);
    k_spmm_w10<<<(NNODES + 255) / 256, 256>>>(bufS0, bufS1, 1);

    // L5
    k_gemm5<<<(NNODES + 255) / 256, 256>>>(bufS1, z, W5, bufS0);
    k_spmm_w10<<<(NNODES + 255) / 256, 256>>>(bufS0, bufS1, 0);
    k_softmax<<<(NNODES + 255) / 256, 256>>>(bufS1, out);
}